// round 2
// baseline (speedup 1.0000x reference)
#include <cuda_runtime.h>
#include <cuda_bf16.h>
#include <math.h>

// Problem constants
#define BDIM 64
#define TSTEPS 512
#define IDIM 512
#define HDIM 1024

// ============================================================
// Kernel 1: xp = embeddings @ Wx^T + bx   -> written into hidden buffer
// A: [M=32768, K=512] row-major, Bw: [N=1024, K=512] row-major (NT gemm)
// Tiles: BM=128, BN=64, BK=16, 256 threads, 8x4 per thread.
// ============================================================
__global__ __launch_bounds__(256) void gemm_xproj(
    const float* __restrict__ A,
    const float* __restrict__ Bw,
    const float* __restrict__ bx,
    float* __restrict__ C)
{
    const int K = IDIM;
    const int N = HDIM;
    __shared__ float As[16][132];
    __shared__ float Bs[16][68];

    const int bm = blockIdx.y * 128;
    const int bn = blockIdx.x * 64;
    const int tid = threadIdx.x;
    const int tx = tid & 15;         // 0..15 -> 4 cols
    const int ty = tid >> 4;         // 0..15 -> 8 rows

    const int arow = tid >> 1;       // 0..127
    const int akq  = (tid & 1) * 2;  // 0 or 2
    const int brow = tid >> 2;       // 0..63
    const int bkq  = tid & 3;        // 0..3

    float acc[8][4];
    #pragma unroll
    for (int i = 0; i < 8; i++)
        #pragma unroll
        for (int j = 0; j < 4; j++) acc[i][j] = 0.0f;

    for (int kt = 0; kt < K; kt += 16) {
        // Load A tile (transposed into smem)
        #pragma unroll
        for (int q = 0; q < 2; q++) {
            float4 v = *(const float4*)(A + (size_t)(bm + arow) * K + kt + (akq + q) * 4);
            As[(akq + q) * 4 + 0][arow] = v.x;
            As[(akq + q) * 4 + 1][arow] = v.y;
            As[(akq + q) * 4 + 2][arow] = v.z;
            As[(akq + q) * 4 + 3][arow] = v.w;
        }
        // Load B tile
        {
            float4 v = *(const float4*)(Bw + (size_t)(bn + brow) * K + kt + bkq * 4);
            Bs[bkq * 4 + 0][brow] = v.x;
            Bs[bkq * 4 + 1][brow] = v.y;
            Bs[bkq * 4 + 2][brow] = v.z;
            Bs[bkq * 4 + 3][brow] = v.w;
        }
        __syncthreads();

        #pragma unroll
        for (int k = 0; k < 16; k++) {
            float4 ar0 = *(const float4*)&As[k][ty * 8];
            float4 ar1 = *(const float4*)&As[k][ty * 8 + 4];
            float4 br  = *(const float4*)&Bs[k][tx * 4];
            float av[8] = {ar0.x, ar0.y, ar0.z, ar0.w, ar1.x, ar1.y, ar1.z, ar1.w};
            float bv[4] = {br.x, br.y, br.z, br.w};
            #pragma unroll
            for (int i = 0; i < 8; i++)
                #pragma unroll
                for (int j = 0; j < 4; j++)
                    acc[i][j] = fmaf(av[i], bv[j], acc[i][j]);
        }
        __syncthreads();
    }

    // Epilogue: add bias, store
    float4 bxv = *(const float4*)(bx + bn + tx * 4);
    #pragma unroll
    for (int i = 0; i < 8; i++) {
        float4 o;
        o.x = acc[i][0] + bxv.x;
        o.y = acc[i][1] + bxv.y;
        o.z = acc[i][2] + bxv.z;
        o.w = acc[i][3] + bxv.w;
        *(float4*)(C + (size_t)(bm + ty * 8 + i) * N + bn + tx * 4) = o;
    }
}

// ============================================================
// Persistent recurrent scan kernel.
// Grid: 128 CTAs x 256 threads (all co-resident on 148+ SMs).
// CTA c owns 8 H-columns [8c, 8c+8). Wh slice held in REGISTERS
// for all 512 steps (8 x 1024 floats / 256 threads = 32 regs/thread).
// Lane layout within warp w (k-range [128w, 128w+128)):
//   hp_idx = lane&3  -> h pair {8c + 2*hp_idx, +1}
//   ksub   = lane>>2 -> 16-k subrange
// Per step: 4 chunks of 16 batches; dot partials, shfl-reduce over ksub,
// smem-reduce over warps, tanh epilogue in-place on hidden (which holds xp).
// ============================================================
__device__ unsigned g_bar_count = 0;
__device__ volatile unsigned g_bar_gen = 0;

__device__ __forceinline__ void grid_sync(unsigned nctas) {
    __threadfence();
    __syncthreads();
    if (threadIdx.x == 0) {
        unsigned my = g_bar_gen;
        unsigned arrived = atomicAdd(&g_bar_count, 1u);
        if (arrived == nctas - 1) {
            g_bar_count = 0;
            __threadfence();
            g_bar_gen = my + 1;
        } else {
            while (g_bar_gen == my) { __nanosleep(32); }
        }
        __threadfence();
    }
    __syncthreads();
}

__global__ __launch_bounds__(256, 1) void rnn_scan(
    float* __restrict__ hidden,      // [B, T, H] holds xp, overwritten with h
    const float* __restrict__ h0,    // [B, H]
    const float* __restrict__ Wh,    // [H, H]
    const float* __restrict__ bh,    // [H]
    float* __restrict__ lasth)       // [B, H]
{
    const int tid = threadIdx.x;
    const int w = tid >> 5;
    const int l = tid & 31;
    const int hp_idx = l & 3;             // 0..3
    const int ksub = l >> 2;              // 0..7
    const int hc = blockIdx.x * 8 + hp_idx * 2;  // first h col of pair
    const int kbase = w * 128 + ksub * 16;

    // Persistent Wh registers: two h-columns x 16 k each
    float wa[16], wb[16];
    #pragma unroll
    for (int q = 0; q < 4; q++) {
        float4 v = *(const float4*)(Wh + (size_t)hc * HDIM + kbase + q * 4);
        wa[q * 4 + 0] = v.x; wa[q * 4 + 1] = v.y;
        wa[q * 4 + 2] = v.z; wa[q * 4 + 3] = v.w;
        float4 u = *(const float4*)(Wh + (size_t)(hc + 1) * HDIM + kbase + q * 4);
        wb[q * 4 + 0] = u.x; wb[q * 4 + 1] = u.y;
        wb[q * 4 + 2] = u.z; wb[q * 4 + 3] = u.w;
    }

    __shared__ float red_s[16][8][9];   // [bi][h][warp] (pad to 9)
    __shared__ float bh_s[8];
    if (tid < 8) bh_s[tid] = bh[blockIdx.x * 8 + tid];
    __syncthreads();

    for (int t = 0; t < TSTEPS; t++) {
        #pragma unroll 1
        for (int chunk = 0; chunk < 4; chunk++) {
            float acc0[16], acc1[16];
            #pragma unroll
            for (int bi = 0; bi < 16; bi++) { acc0[bi] = 0.0f; acc1[bi] = 0.0f; }

            #pragma unroll
            for (int bi = 0; bi < 16; bi++) {
                const int b = chunk * 16 + bi;
                const float4* hv = (t == 0)
                    ? (const float4*)(h0 + (size_t)b * HDIM + kbase)
                    : (const float4*)(hidden + (size_t)b * (TSTEPS * HDIM)
                                             + (size_t)(t - 1) * HDIM + kbase);
                #pragma unroll
                for (int q = 0; q < 4; q++) {
                    float4 v = __ldg(hv + q);
                    acc0[bi] = fmaf(v.x, wa[q * 4 + 0], acc0[bi]);
                    acc0[bi] = fmaf(v.y, wa[q * 4 + 1], acc0[bi]);
                    acc0[bi] = fmaf(v.z, wa[q * 4 + 2], acc0[bi]);
                    acc0[bi] = fmaf(v.w, wa[q * 4 + 3], acc0[bi]);
                    acc1[bi] = fmaf(v.x, wb[q * 4 + 0], acc1[bi]);
                    acc1[bi] = fmaf(v.y, wb[q * 4 + 1], acc1[bi]);
                    acc1[bi] = fmaf(v.z, wb[q * 4 + 2], acc1[bi]);
                    acc1[bi] = fmaf(v.w, wb[q * 4 + 3], acc1[bi]);
                }
            }

            // Reduce over ksub (lane bits 2..4): xor-shuffles 4, 8, 16
            #pragma unroll
            for (int bi = 0; bi < 16; bi++) {
                #pragma unroll
                for (int s = 4; s < 32; s <<= 1) {
                    acc0[bi] += __shfl_xor_sync(0xffffffffu, acc0[bi], s);
                    acc1[bi] += __shfl_xor_sync(0xffffffffu, acc1[bi], s);
                }
            }

            // Each ksub-group stores 2 batches worth (all combos covered)
            {
                const int b0 = ksub * 2;
                red_s[b0][hp_idx * 2][w]         = acc0[b0];
                red_s[b0][hp_idx * 2 + 1][w]     = acc1[b0];
                red_s[b0 + 1][hp_idx * 2][w]     = acc0[b0 + 1];
                red_s[b0 + 1][hp_idx * 2 + 1][w] = acc1[b0 + 1];
            }
            __syncthreads();

            // Final: 128 threads finish 16b x 8h outputs: sum warps, +xp +bh, tanh
            if (tid < 128) {
                const int bi = tid >> 3;
                const int hl = tid & 7;
                float s = 0.0f;
                #pragma unroll
                for (int ww = 0; ww < 8; ww++) s += red_s[bi][hl][ww];
                const int b = chunk * 16 + bi;
                const size_t oidx = (size_t)b * (TSTEPS * HDIM)
                                  + (size_t)t * HDIM + blockIdx.x * 8 + hl;
                const float val = tanhf(hidden[oidx] + s + bh_s[hl]);
                hidden[oidx] = val;
                if (t == TSTEPS - 1)
                    lasth[(size_t)b * HDIM + blockIdx.x * 8 + hl] = val;
            }
            __syncthreads();
        }
        grid_sync(gridDim.x);
    }
}

// ============================================================
// Launch
// ============================================================
extern "C" void kernel_launch(void* const* d_in, const int* in_sizes, int n_in,
                              void* d_out, int out_size) {
    const float* emb = (const float*)d_in[0];   // [B,T,I]
    const float* h0  = (const float*)d_in[1];   // [B,H]
    const float* Wx  = (const float*)d_in[2];   // [H,I]
    const float* bx  = (const float*)d_in[3];   // [H]
    const float* Wh  = (const float*)d_in[4];   // [H,H]
    const float* bh  = (const float*)d_in[5];   // [H]

    float* hidden = (float*)d_out;                            // [B,T,H]
    float* lasth  = hidden + (size_t)BDIM * TSTEPS * HDIM;    // [B,H]

    // xp = emb @ Wx^T + bx, written into hidden
    dim3 g1(HDIM / 64, (BDIM * TSTEPS) / 128);
    gemm_xproj<<<g1, 256>>>(emb, Wx, bx, hidden);

    // sequential scan, persistent kernel with software grid barrier
    rnn_scan<<<128, 256>>>(hidden, h0, Wh, bh, lasth);
}

// round 3
// speedup vs baseline: 1.6491x; 1.6491x over previous
#include <cuda_runtime.h>
#include <cuda_bf16.h>
#include <math.h>

// Problem constants
#define BDIM 64
#define TSTEPS 512
#define IDIM 512
#define HDIM 1024

#define NCTAS 128
#define NTHREADS 512

// ============================================================
// Kernel 1: xp = embeddings @ Wx^T + bx   -> written into hidden buffer
// A: [M=32768, K=512] row-major, Bw: [N=1024, K=512] row-major (NT gemm)
// Tiles: BM=128, BN=64, BK=16, 256 threads, 8x4 per thread.
// ============================================================
__global__ __launch_bounds__(256) void gemm_xproj(
    const float* __restrict__ A,
    const float* __restrict__ Bw,
    const float* __restrict__ bx,
    float* __restrict__ C)
{
    const int K = IDIM;
    const int N = HDIM;
    __shared__ float As[16][132];
    __shared__ float Bs[16][68];

    const int bm = blockIdx.y * 128;
    const int bn = blockIdx.x * 64;
    const int tid = threadIdx.x;
    const int tx = tid & 15;         // 0..15 -> 4 cols
    const int ty = tid >> 4;         // 0..15 -> 8 rows

    const int arow = tid >> 1;       // 0..127
    const int akq  = (tid & 1) * 2;  // 0 or 2
    const int brow = tid >> 2;       // 0..63
    const int bkq  = tid & 3;        // 0..3

    float acc[8][4];
    #pragma unroll
    for (int i = 0; i < 8; i++)
        #pragma unroll
        for (int j = 0; j < 4; j++) acc[i][j] = 0.0f;

    for (int kt = 0; kt < K; kt += 16) {
        #pragma unroll
        for (int q = 0; q < 2; q++) {
            float4 v = *(const float4*)(A + (size_t)(bm + arow) * K + kt + (akq + q) * 4);
            As[(akq + q) * 4 + 0][arow] = v.x;
            As[(akq + q) * 4 + 1][arow] = v.y;
            As[(akq + q) * 4 + 2][arow] = v.z;
            As[(akq + q) * 4 + 3][arow] = v.w;
        }
        {
            float4 v = *(const float4*)(Bw + (size_t)(bn + brow) * K + kt + bkq * 4);
            Bs[bkq * 4 + 0][brow] = v.x;
            Bs[bkq * 4 + 1][brow] = v.y;
            Bs[bkq * 4 + 2][brow] = v.z;
            Bs[bkq * 4 + 3][brow] = v.w;
        }
        __syncthreads();

        #pragma unroll
        for (int k = 0; k < 16; k++) {
            float4 ar0 = *(const float4*)&As[k][ty * 8];
            float4 ar1 = *(const float4*)&As[k][ty * 8 + 4];
            float4 br  = *(const float4*)&Bs[k][tx * 4];
            float av[8] = {ar0.x, ar0.y, ar0.z, ar0.w, ar1.x, ar1.y, ar1.z, ar1.w};
            float bv[4] = {br.x, br.y, br.z, br.w};
            #pragma unroll
            for (int i = 0; i < 8; i++)
                #pragma unroll
                for (int j = 0; j < 4; j++)
                    acc[i][j] = fmaf(av[i], bv[j], acc[i][j]);
        }
        __syncthreads();
    }

    float4 bxv = *(const float4*)(bx + bn + tx * 4);
    #pragma unroll
    for (int i = 0; i < 8; i++) {
        float4 o;
        o.x = acc[i][0] + bxv.x;
        o.y = acc[i][1] + bxv.y;
        o.z = acc[i][2] + bxv.z;
        o.w = acc[i][3] + bxv.w;
        *(float4*)(C + (size_t)(bm + ty * 8 + i) * N + bn + tx * 4) = o;
    }
}

// ============================================================
// Persistent recurrent scan, v2.
// Grid: 128 CTAs x 512 threads. CTA = (batch-group gb of 16 batches) x
// (col-group cg of 32 H-columns).  gb = bid & 3, cg = bid >> 2.
// Warp w owns k-range [64w, 64w+64); lane l owns column cg*32+l.
// Wh slice per lane: 64 floats in registers (persistent across 512 steps).
// Per step:
//   1. cooperative coalesced stage of h_prev[16 batches][1024] into smem
//   2. each lane: 16 full-k partial dot products (64 FMA each), no shuffles
//   3. smem reduce over 16 warps, + xp + bh, tanh, store in place
//   4. grid barrier (tight poll, no nanosleep)
// ============================================================
__device__ unsigned g_bar_count = 0;
__device__ volatile unsigned g_bar_gen = 0;

__device__ __forceinline__ void grid_sync(unsigned nctas) {
    __syncthreads();
    if (threadIdx.x == 0) {
        __threadfence();
        unsigned my = g_bar_gen;
        if (atomicAdd(&g_bar_count, 1u) == nctas - 1) {
            g_bar_count = 0;
            __threadfence();
            g_bar_gen = my + 1;
        } else {
            while (g_bar_gen == my) { /* tight poll */ }
        }
        __threadfence();
    }
    __syncthreads();
}

// smem: h_s [16][1024] floats (64KB) + red_s [16][32][17] floats (34.8KB)
#define HS_FLOATS   (16 * 1024)
#define RED_FLOATS  (16 * 32 * 17)
#define SMEM_BYTES  ((HS_FLOATS + RED_FLOATS) * 4)

__global__ __launch_bounds__(NTHREADS, 1) void rnn_scan(
    float* __restrict__ hidden,      // [B, T, H] holds xp, overwritten with h
    const float* __restrict__ h0,    // [B, H]
    const float* __restrict__ Wh,    // [H, H]
    const float* __restrict__ bh,    // [H]
    float* __restrict__ lasth)       // [B, H]
{
    extern __shared__ float smem[];
    float* h_s   = smem;               // [16][1024]
    float* red_s = smem + HS_FLOATS;   // [bi][col][warp] padded to 17

    const int tid = threadIdx.x;
    const int w = tid >> 5;            // warp 0..15  -> k range [64w, 64w+64)
    const int l = tid & 31;            // lane 0..31  -> local column
    const int gb = blockIdx.x & 3;     // batch group (16 batches)
    const int cg = blockIdx.x >> 2;    // col group   (32 columns)
    const int b0 = gb * 16;
    const int hcol = cg * 32 + l;      // this lane's H column
    const int kbase = w * 64;

    // Persistent Wh registers: Wh[hcol][kbase .. kbase+64)
    float wreg[64];
    #pragma unroll
    for (int q = 0; q < 16; q++) {
        float4 v = *(const float4*)(Wh + (size_t)hcol * HDIM + kbase + q * 4);
        wreg[q * 4 + 0] = v.x;
        wreg[q * 4 + 1] = v.y;
        wreg[q * 4 + 2] = v.z;
        wreg[q * 4 + 3] = v.w;
    }

    // Epilogue constants for this thread: output (b_e, h_e)
    const int bi_e = tid >> 5;                 // 0..15 (one batch per warp)
    const int col_e = tid & 31;                // 0..31
    const int b_e = b0 + bi_e;
    const int h_e = cg * 32 + col_e;
    const float bh_r = bh[h_e];

    for (int t = 0; t < TSTEPS; t++) {
        // ---- stage h_prev[16][1024] into smem (coalesced float4) ----
        if (t == 0) {
            #pragma unroll
            for (int i = 0; i < 8; i++) {
                int idx = tid + NTHREADS * i;        // 0..4095 float4 slots
                int r = idx >> 8;                    // batch row 0..15
                int c = (idx & 255) << 2;            // float offset
                float4 v = *(const float4*)(h0 + (size_t)(b0 + r) * HDIM + c);
                *(float4*)(h_s + r * HDIM + c) = v;
            }
        } else {
            #pragma unroll
            for (int i = 0; i < 8; i++) {
                int idx = tid + NTHREADS * i;
                int r = idx >> 8;
                int c = (idx & 255) << 2;
                float4 v = *(const float4*)(hidden
                          + ((size_t)(b0 + r) * TSTEPS + (t - 1)) * HDIM + c);
                *(float4*)(h_s + r * HDIM + c) = v;
            }
        }
        __syncthreads();

        // ---- partial dot products: 16 batches x 64 k, no shuffles ----
        #pragma unroll 4
        for (int bi = 0; bi < 16; bi++) {
            const float4* hp = (const float4*)(h_s + bi * HDIM + kbase);
            float s0 = 0.0f, s1 = 0.0f;
            #pragma unroll
            for (int q = 0; q < 16; q++) {
                float4 v = hp[q];
                s0 = fmaf(v.x, wreg[q * 4 + 0], s0);
                s1 = fmaf(v.y, wreg[q * 4 + 1], s1);
                s0 = fmaf(v.z, wreg[q * 4 + 2], s0);
                s1 = fmaf(v.w, wreg[q * 4 + 3], s1);
            }
            red_s[(bi * 32 + l) * 17 + w] = s0 + s1;
        }
        __syncthreads();

        // ---- final reduce over 16 warps, epilogue, in-place store ----
        {
            const float* rp = red_s + (bi_e * 32 + col_e) * 17;
            float s = 0.0f;
            #pragma unroll
            for (int ww = 0; ww < 16; ww++) s += rp[ww];
            const size_t oidx = ((size_t)b_e * TSTEPS + t) * HDIM + h_e;
            const float val = tanhf(hidden[oidx] + s + bh_r);
            hidden[oidx] = val;
            if (t == TSTEPS - 1)
                lasth[(size_t)b_e * HDIM + h_e] = val;
        }

        grid_sync(NCTAS);
    }
}

// ============================================================
// Launch
// ============================================================
extern "C" void kernel_launch(void* const* d_in, const int* in_sizes, int n_in,
                              void* d_out, int out_size) {
    const float* emb = (const float*)d_in[0];   // [B,T,I]
    const float* h0  = (const float*)d_in[1];   // [B,H]
    const float* Wx  = (const float*)d_in[2];   // [H,I]
    const float* bx  = (const float*)d_in[3];   // [H]
    const float* Wh  = (const float*)d_in[4];   // [H,H]
    const float* bh  = (const float*)d_in[5];   // [H]

    float* hidden = (float*)d_out;                            // [B,T,H]
    float* lasth  = hidden + (size_t)BDIM * TSTEPS * HDIM;    // [B,H]

    // allow >48KB dynamic smem for the scan (idempotent, graph-safe)
    cudaFuncSetAttribute(rnn_scan, cudaFuncAttributeMaxDynamicSharedMemorySize,
                         SMEM_BYTES);

    // xp = emb @ Wx^T + bx, written into hidden
    dim3 g1(HDIM / 64, (BDIM * TSTEPS) / 128);
    gemm_xproj<<<g1, 256>>>(emb, Wx, bx, hidden);

    // sequential scan, persistent kernel with software grid barrier
    rnn_scan<<<NCTAS, NTHREADS, SMEM_BYTES>>>(hidden, h0, Wh, bh, lasth);
}

// round 4
// speedup vs baseline: 1.6563x; 1.0044x over previous
#include <cuda_runtime.h>
#include <cuda_bf16.h>
#include <math.h>

// Problem constants
#define BDIM 64
#define TSTEPS 512
#define IDIM 512
#define HDIM 1024

#define NCTAS 128
#define NTHREADS 512

typedef unsigned long long ull;

// ---------- packed f32x2 helpers ----------
__device__ __forceinline__ ull ffma2(ull a, ull b, ull c) {
    ull d;
    asm("fma.rn.f32x2 %0, %1, %2, %3;" : "=l"(d) : "l"(a), "l"(b), "l"(c));
    return d;
}
__device__ __forceinline__ float lo_f(ull v) {
    return __uint_as_float((unsigned)(v & 0xffffffffull));
}
__device__ __forceinline__ float hi_f(ull v) {
    return __uint_as_float((unsigned)(v >> 32));
}
__device__ __forceinline__ ull dup_f(float x) {
    unsigned u = __float_as_uint(x);
    return ((ull)u << 32) | u;
}
__device__ __forceinline__ unsigned ld_relaxed(const unsigned* p) {
    unsigned v;
    asm volatile("ld.relaxed.gpu.u32 %0, [%1];" : "=r"(v) : "l"(p));
    return v;
}

// ============================================================
// Kernel 1: xp = embeddings @ Wx^T + bx  (written into hidden buffer)
// NT gemm, BM=128 BN=64 BK=16, 256 threads, FFMA2 inner (rows packed).
// ============================================================
__global__ __launch_bounds__(256) void gemm_xproj(
    const float* __restrict__ A,
    const float* __restrict__ Bw,
    const float* __restrict__ bx,
    float* __restrict__ C)
{
    const int K = IDIM;
    const int N = HDIM;
    __shared__ float As[16][132];
    __shared__ ull   Bs[16][68];   // duplicated-pack (b,b)

    const int bm = blockIdx.y * 128;
    const int bn = blockIdx.x * 64;
    const int tid = threadIdx.x;
    const int tx = tid & 15;         // 4 cols
    const int ty = tid >> 4;         // 8 rows (4 row-pairs)

    const int arow = tid >> 1;
    const int akq  = (tid & 1) * 2;
    const int brow = tid >> 2;
    const int bkq  = tid & 3;

    ull accp[4][4];                  // [row-pair][col] packed
    #pragma unroll
    for (int i = 0; i < 4; i++)
        #pragma unroll
        for (int j = 0; j < 4; j++) accp[i][j] = 0ull;

    for (int kt = 0; kt < K; kt += 16) {
        #pragma unroll
        for (int q = 0; q < 2; q++) {
            float4 v = *(const float4*)(A + (size_t)(bm + arow) * K + kt + (akq + q) * 4);
            As[(akq + q) * 4 + 0][arow] = v.x;
            As[(akq + q) * 4 + 1][arow] = v.y;
            As[(akq + q) * 4 + 2][arow] = v.z;
            As[(akq + q) * 4 + 3][arow] = v.w;
        }
        {
            float4 v = *(const float4*)(Bw + (size_t)(bn + brow) * K + kt + bkq * 4);
            Bs[bkq * 4 + 0][brow] = dup_f(v.x);
            Bs[bkq * 4 + 1][brow] = dup_f(v.y);
            Bs[bkq * 4 + 2][brow] = dup_f(v.z);
            Bs[bkq * 4 + 3][brow] = dup_f(v.w);
        }
        __syncthreads();

        #pragma unroll
        for (int k = 0; k < 16; k++) {
            ulonglong2 ar0 = *(const ulonglong2*)&As[k][ty * 8];     // rows (0,1),(2,3)
            ulonglong2 ar1 = *(const ulonglong2*)&As[k][ty * 8 + 4]; // rows (4,5),(6,7)
            ull ap[4] = {ar0.x, ar0.y, ar1.x, ar1.y};
            ull bd[4] = {Bs[k][tx * 4 + 0], Bs[k][tx * 4 + 1],
                         Bs[k][tx * 4 + 2], Bs[k][tx * 4 + 3]};
            #pragma unroll
            for (int i = 0; i < 4; i++)
                #pragma unroll
                for (int j = 0; j < 4; j++)
                    accp[i][j] = ffma2(ap[i], bd[j], accp[i][j]);
        }
        __syncthreads();
    }

    float4 bxv = *(const float4*)(bx + bn + tx * 4);
    #pragma unroll
    for (int i = 0; i < 4; i++) {
        float4 o0, o1;  // rows 2i, 2i+1
        o0.x = lo_f(accp[i][0]) + bxv.x;  o1.x = hi_f(accp[i][0]) + bxv.x;
        o0.y = lo_f(accp[i][1]) + bxv.y;  o1.y = hi_f(accp[i][1]) + bxv.y;
        o0.z = lo_f(accp[i][2]) + bxv.z;  o1.z = hi_f(accp[i][2]) + bxv.z;
        o0.w = lo_f(accp[i][3]) + bxv.w;  o1.w = hi_f(accp[i][3]) + bxv.w;
        *(float4*)(C + (size_t)(bm + ty * 8 + 2 * i + 0) * N + bn + tx * 4) = o0;
        *(float4*)(C + (size_t)(bm + ty * 8 + 2 * i + 1) * N + bn + tx * 4) = o1;
    }
}

// ============================================================
// Dataflow-synced recurrent scan.
// 128 CTAs x 512 threads. CTA = (batch-group gb: 16 batches) x
// (col-group cg: 32 H columns). gb = bid & 3, cg = bid >> 2.
// Forward-only sync: per-group monotonic counter g_flag[gb].
//   producer: write h_t slice, __threadfence, atomicAdd(+1)
//   consumer: poll flag >= 32*t before staging h_{t-1} via __ldcg
// Inner math: packed fma.rn.f32x2, k-pairs come pre-packed from
// 128-bit smem loads. Zero shuffles, zero packing MOVs.
// ============================================================
__device__ unsigned g_flag[4];

__global__ void init_flags() {
    if (threadIdx.x < 4) g_flag[threadIdx.x] = 0u;
}

#define HS_FLOATS   (16 * 1024)
#define RED_FLOATS  (16 * 32 * 17)
#define SMEM_BYTES  ((HS_FLOATS + RED_FLOATS) * 4)

__global__ __launch_bounds__(NTHREADS, 1) void rnn_scan(
    float* __restrict__ hidden,      // [B, T, H] holds xp, overwritten with h
    const float* __restrict__ h0,    // [B, H]
    const float* __restrict__ Wh,    // [H, H]
    const float* __restrict__ bh,    // [H]
    float* __restrict__ lasth)       // [B, H]
{
    extern __shared__ float smem[];
    float* h_s   = smem;               // [16][1024]
    float* red_s = smem + HS_FLOATS;   // [bi][col][warp] pad 17

    const int tid = threadIdx.x;
    const int w = tid >> 5;            // warp 0..15 -> k range [64w, 64w+64)
    const int l = tid & 31;            // lane -> local column
    const int gb = blockIdx.x & 3;     // batch group
    const int cg = blockIdx.x >> 2;    // col group
    const int b0 = gb * 16;
    const int hcol = cg * 32 + l;
    const int kbase = w * 64;

    // Persistent packed Wh: wp[j] = (Wh[hcol][kbase+2j], Wh[hcol][kbase+2j+1])
    ull wp[32];
    #pragma unroll
    for (int q = 0; q < 16; q++) {
        ulonglong2 v = *(const ulonglong2*)(Wh + (size_t)hcol * HDIM + kbase + q * 4);
        wp[2 * q + 0] = v.x;
        wp[2 * q + 1] = v.y;
    }

    // Epilogue mapping: thread -> (batch bi_e, col col_e)
    const int bi_e = tid >> 5;
    const int col_e = tid & 31;
    const int b_e = b0 + bi_e;
    const int h_e = cg * 32 + col_e;
    const float bh_r = bh[h_e];

    for (int t = 0; t < TSTEPS; t++) {
        // ---- wait for h_{t-1} from all 32 col-CTAs of this group ----
        if (t > 0 && tid == 0) {
            const unsigned target = 32u * (unsigned)t;
            while (ld_relaxed(&g_flag[gb]) < target) { }
            __threadfence();
        }
        __syncthreads();

        // ---- stage h_prev[16][1024] into smem (L2-only loads) ----
        if (t == 0) {
            #pragma unroll
            for (int i = 0; i < 8; i++) {
                int idx = tid + NTHREADS * i;
                int r = idx >> 8;
                int c = (idx & 255) << 2;
                float4 v = __ldcg((const float4*)(h0 + (size_t)(b0 + r) * HDIM + c));
                *(float4*)(h_s + r * HDIM + c) = v;
            }
        } else {
            #pragma unroll
            for (int i = 0; i < 8; i++) {
                int idx = tid + NTHREADS * i;
                int r = idx >> 8;
                int c = (idx & 255) << 2;
                float4 v = __ldcg((const float4*)(hidden
                          + ((size_t)(b0 + r) * TSTEPS + (t - 1)) * HDIM + c));
                *(float4*)(h_s + r * HDIM + c) = v;
            }
        }

        // xp for this step is independent of h_prev: issue load early
        const size_t oidx = ((size_t)b_e * TSTEPS + t) * HDIM + h_e;
        const float xp_val = __ldcg(hidden + oidx);

        __syncthreads();

        // ---- partial dots: 16 batches x 64 k, packed f32x2 ----
        #pragma unroll 2
        for (int bi = 0; bi < 16; bi++) {
            const ulonglong2* hp = (const ulonglong2*)(h_s + bi * HDIM + kbase);
            ull a0 = 0ull, a1 = 0ull;
            #pragma unroll
            for (int q = 0; q < 16; q++) {
                ulonglong2 v = hp[q];           // (h2q0,h2q0+1),(h2q0+2,h2q0+3)
                a0 = ffma2(v.x, wp[2 * q + 0], a0);
                a1 = ffma2(v.y, wp[2 * q + 1], a1);
            }
            red_s[(bi * 32 + l) * 17 + w] =
                (lo_f(a0) + hi_f(a0)) + (lo_f(a1) + hi_f(a1));
        }
        __syncthreads();

        // ---- reduce over 16 warps, epilogue, store ----
        {
            const float* rp = red_s + (bi_e * 32 + col_e) * 17;
            float s = 0.0f;
            #pragma unroll
            for (int ww = 0; ww < 16; ww++) s += rp[ww];
            const float val = tanhf(xp_val + s + bh_r);
            hidden[oidx] = val;
            if (t == TSTEPS - 1)
                lasth[(size_t)b_e * HDIM + h_e] = val;
        }

        // ---- publish: fence all stores, then bump group counter ----
        __threadfence();
        __syncthreads();
        if (tid == 0) atomicAdd(&g_flag[gb], 1u);
    }
}

// ============================================================
// Launch
// ============================================================
extern "C" void kernel_launch(void* const* d_in, const int* in_sizes, int n_in,
                              void* d_out, int out_size) {
    const float* emb = (const float*)d_in[0];   // [B,T,I]
    const float* h0  = (const float*)d_in[1];   // [B,H]
    const float* Wx  = (const float*)d_in[2];   // [H,I]
    const float* bx  = (const float*)d_in[3];   // [H]
    const float* Wh  = (const float*)d_in[4];   // [H,H]
    const float* bh  = (const float*)d_in[5];   // [H]

    float* hidden = (float*)d_out;                            // [B,T,H]
    float* lasth  = hidden + (size_t)BDIM * TSTEPS * HDIM;    // [B,H]

    cudaFuncSetAttribute(rnn_scan, cudaFuncAttributeMaxDynamicSharedMemorySize,
                         SMEM_BYTES);

    init_flags<<<1, 32>>>();

    dim3 g1(HDIM / 64, (BDIM * TSTEPS) / 128);
    gemm_xproj<<<g1, 256>>>(emb, Wx, bx, hidden);

    rnn_scan<<<NCTAS, NTHREADS, SMEM_BYTES>>>(hidden, h0, Wh, bh, lasth);
}

// round 5
// speedup vs baseline: 1.6615x; 1.0031x over previous
#include <cuda_runtime.h>
#include <cuda_bf16.h>
#include <math.h>

// Problem constants
#define BDIM 64
#define TSTEPS 512
#define IDIM 512
#define HDIM 1024

#define NCTAS 128
#define NTHREADS 512

typedef unsigned long long ull;

// ---------- packed f32x2 helpers ----------
__device__ __forceinline__ ull ffma2(ull a, ull b, ull c) {
    ull d;
    asm("fma.rn.f32x2 %0, %1, %2, %3;" : "=l"(d) : "l"(a), "l"(b), "l"(c));
    return d;
}
__device__ __forceinline__ ull fadd2(ull a, ull b) {
    ull d;
    asm("add.rn.f32x2 %0, %1, %2;" : "=l"(d) : "l"(a), "l"(b));
    return d;
}
__device__ __forceinline__ float lo_f(ull v) {
    return __uint_as_float((unsigned)(v & 0xffffffffull));
}
__device__ __forceinline__ float hi_f(ull v) {
    return __uint_as_float((unsigned)(v >> 32));
}
__device__ __forceinline__ ull dup_f(float x) {
    unsigned u = __float_as_uint(x);
    return ((ull)u << 32) | u;
}
__device__ __forceinline__ unsigned ld_acq(const unsigned* p) {
    unsigned v;
    asm volatile("ld.acquire.gpu.global.u32 %0, [%1];" : "=r"(v) : "l"(p) : "memory");
    return v;
}
__device__ __forceinline__ void red_rel_add1(unsigned* p) {
    asm volatile("red.release.gpu.global.add.u32 [%0], 1;" :: "l"(p) : "memory");
}

// Flags: [gb][chunk], each padded to its own 128B sector
__device__ unsigned g_flag[16 * 32];
#define FLAG_IDX(gb, c) (((gb) * 4 + (c)) * 32)

// ============================================================
// Kernel 1: xp = embeddings @ Wx^T + bx  -> written into hidden
// NT gemm, BM=128 BN=128 BK=16, 256 threads, 8x8/thread, FFMA2.
// Also resets the scan flags (block (0,0)).
// ============================================================
__global__ __launch_bounds__(256) void gemm_xproj(
    const float* __restrict__ A,
    const float* __restrict__ Bw,
    const float* __restrict__ bx,
    float* __restrict__ C)
{
    if (blockIdx.x == 0 && blockIdx.y == 0 && threadIdx.x < 16)
        g_flag[threadIdx.x * 32] = 0u;

    const int K = IDIM;
    const int N = HDIM;
    __shared__ ull   As_d[16][130];   // duplicated-pack rows: (a,a)
    __shared__ float Bs[16][132];

    const int bm = blockIdx.y * 128;
    const int bn = blockIdx.x * 128;
    const int tid = threadIdx.x;
    const int tx = tid & 15;          // 8 cols
    const int ty = tid >> 4;          // 8 rows

    ull acc[8][4];                    // [row][colpair]
    #pragma unroll
    for (int i = 0; i < 8; i++)
        #pragma unroll
        for (int j = 0; j < 4; j++) acc[i][j] = 0ull;

    for (int kt = 0; kt < K; kt += 16) {
        #pragma unroll
        for (int i = 0; i < 2; i++) {
            int f = tid + 256 * i;            // 0..511
            int row = f >> 2, quad = f & 3;
            float4 v = *(const float4*)(A + (size_t)(bm + row) * K + kt + quad * 4);
            As_d[quad * 4 + 0][row] = dup_f(v.x);
            As_d[quad * 4 + 1][row] = dup_f(v.y);
            As_d[quad * 4 + 2][row] = dup_f(v.z);
            As_d[quad * 4 + 3][row] = dup_f(v.w);
        }
        #pragma unroll
        for (int i = 0; i < 2; i++) {
            int f = tid + 256 * i;
            int col = f >> 2, quad = f & 3;
            float4 v = *(const float4*)(Bw + (size_t)(bn + col) * K + kt + quad * 4);
            Bs[quad * 4 + 0][col] = v.x;
            Bs[quad * 4 + 1][col] = v.y;
            Bs[quad * 4 + 2][col] = v.z;
            Bs[quad * 4 + 3][col] = v.w;
        }
        __syncthreads();

        #pragma unroll
        for (int k = 0; k < 16; k++) {
            ulonglong2 a01 = *(const ulonglong2*)&As_d[k][ty * 8 + 0];
            ulonglong2 a23 = *(const ulonglong2*)&As_d[k][ty * 8 + 2];
            ulonglong2 a45 = *(const ulonglong2*)&As_d[k][ty * 8 + 4];
            ulonglong2 a67 = *(const ulonglong2*)&As_d[k][ty * 8 + 6];
            ulonglong2 b03 = *(const ulonglong2*)&Bs[k][tx * 8 + 0];
            ulonglong2 b47 = *(const ulonglong2*)&Bs[k][tx * 8 + 4];
            ull ad[8] = {a01.x, a01.y, a23.x, a23.y, a45.x, a45.y, a67.x, a67.y};
            ull bp[4] = {b03.x, b03.y, b47.x, b47.y};
            #pragma unroll
            for (int i = 0; i < 8; i++)
                #pragma unroll
                for (int j = 0; j < 4; j++)
                    acc[i][j] = ffma2(ad[i], bp[j], acc[i][j]);
        }
        __syncthreads();
    }

    float4 bx0 = *(const float4*)(bx + bn + tx * 8);
    float4 bx1 = *(const float4*)(bx + bn + tx * 8 + 4);
    #pragma unroll
    for (int i = 0; i < 8; i++) {
        float4 o0, o1;
        o0.x = lo_f(acc[i][0]) + bx0.x;
        o0.y = hi_f(acc[i][0]) + bx0.y;
        o0.z = lo_f(acc[i][1]) + bx0.z;
        o0.w = hi_f(acc[i][1]) + bx0.w;
        o1.x = lo_f(acc[i][2]) + bx1.x;
        o1.y = hi_f(acc[i][2]) + bx1.y;
        o1.z = lo_f(acc[i][3]) + bx1.z;
        o1.w = hi_f(acc[i][3]) + bx1.w;
        float* cp = C + (size_t)(bm + ty * 8 + i) * N + bn + tx * 8;
        *(float4*)(cp)     = o0;
        *(float4*)(cp + 4) = o1;
    }
}

// ============================================================
// Chunked dataflow recurrent scan.
// 128 CTAs x 512 threads. CTA = (gb: 16 batches) x (cg: 32 H cols).
// h_prev split into 4 k-chunks of 256; chunk c published by col-CTAs
// [8c, 8c+8) under flag g_flag[gb][c]. Consumer computes chunk c while
// staging chunk c+1 (double-buffered smem) and polling chunk c+2.
// Inner math packed fma.rn.f32x2; Wh slice persistent in registers.
// ============================================================
#define HC_FLOATS  (2 * 16 * 256)          // double-buffered h chunk
#define RED_FLOATS (16 * 32 * 17)
#define SMEM_BYTES ((HC_FLOATS + RED_FLOATS) * 4)

__global__ __launch_bounds__(NTHREADS, 1) void rnn_scan(
    float* __restrict__ hidden,      // [B, T, H] holds xp, overwritten with h
    const float* __restrict__ h0,    // [B, H]
    const float* __restrict__ Wh,    // [H, H]
    const float* __restrict__ bh,    // [H]
    float* __restrict__ lasth)       // [B, H]
{
    extern __shared__ float smem[];
    float* h_c   = smem;               // [2][16][256]
    float* red_s = smem + HC_FLOATS;   // [bi][col][warp] pad 17

    const int tid = threadIdx.x;
    const int w = tid >> 5;            // warp 0..15: k-local [16w,16w+16) per chunk
    const int l = tid & 31;            // lane -> local column
    const int gb = blockIdx.x & 3;     // batch group (16 batches)
    const int cg = blockIdx.x >> 2;    // col group (32 cols)
    const int b0 = gb * 16;
    const int hcol = cg * 32 + l;
    const int my_flag = FLAG_IDX(gb, cg >> 3);

    // Persistent packed Wh: wp[c*8+j] = (Wh[hcol][c*256+w*16+2j], +1)
    ull wp[32];
    #pragma unroll
    for (int c = 0; c < 4; c++) {
        const float* src = Wh + (size_t)hcol * HDIM + c * 256 + w * 16;
        #pragma unroll
        for (int q = 0; q < 2; q++) {
            ulonglong2 v = *(const ulonglong2*)(src + q * 8);
            wp[c * 8 + q * 4 + 0] = v.x;
            wp[c * 8 + q * 4 + 1] = v.y;
            ulonglong2 u = *(const ulonglong2*)(src + q * 8 + 4);
            wp[c * 8 + q * 4 + 2] = u.x;
            wp[c * 8 + q * 4 + 3] = u.y;
        }
    }

    // Epilogue mapping: thread -> (batch bi_e, col col_e)
    const int bi_e = tid >> 5;
    const int col_e = tid & 31;
    const int b_e = b0 + bi_e;
    const int h_e = cg * 32 + col_e;
    const float bh_r = bh[h_e];

    // Stage indices (1024 float4 per chunk; 2 per thread)
    const int s_r0 = tid >> 6;                 // row for idx=tid
    const int s_q0 = tid & 63;
    const int s_r1 = (tid + 512) >> 6;
    const int s_q1 = (tid + 512) & 63;

    float acc[16];

    for (int t = 0; t < TSTEPS; t++) {
        const unsigned target = 8u * (unsigned)t;

        // ---- wait chunk0, stage chunk0; wait chunk1 ----
        if (t > 0 && tid == 0)
            while (ld_acq(&g_flag[FLAG_IDX(gb, 0)]) < target) { }
        __syncthreads();

        #pragma unroll
        for (int bi = 0; bi < 16; bi++) acc[bi] = 0.0f;

        {
            const float* base = (t == 0)
                ? (h0 + (size_t)b0 * HDIM)
                : (hidden + ((size_t)b0 * TSTEPS + (t - 1)) * HDIM);
            const size_t rstride = (t == 0) ? (size_t)HDIM : (size_t)TSTEPS * HDIM;
            float4 v0 = __ldcg((const float4*)(base + s_r0 * rstride + s_q0 * 4));
            float4 v1 = __ldcg((const float4*)(base + s_r1 * rstride + s_q1 * 4));
            *(float4*)(h_c + s_r0 * 256 + s_q0 * 4) = v0;
            *(float4*)(h_c + s_r1 * 256 + s_q1 * 4) = v1;
        }
        if (t > 0 && tid == 0)
            while (ld_acq(&g_flag[FLAG_IDX(gb, 1)]) < target) { }

        // xp for this step (independent of h_prev): issue early
        const size_t oidx = ((size_t)b_e * TSTEPS + t) * HDIM + h_e;
        const float xp_val = __ldg(hidden + oidx);

        __syncthreads();   // chunk0 staged; chunk1 flag acquired

        #pragma unroll
        for (int c = 0; c < 4; c++) {
            // stage chunk c+1 into the other buffer (loads fly under compute)
            if (c < 3) {
                const float* base = (t == 0)
                    ? (h0 + (size_t)b0 * HDIM + (c + 1) * 256)
                    : (hidden + ((size_t)b0 * TSTEPS + (t - 1)) * HDIM + (c + 1) * 256);
                const size_t rstride = (t == 0) ? (size_t)HDIM : (size_t)TSTEPS * HDIM;
                float* dst = h_c + ((c + 1) & 1) * (16 * 256);
                float4 v0 = __ldcg((const float4*)(base + s_r0 * rstride + s_q0 * 4));
                float4 v1 = __ldcg((const float4*)(base + s_r1 * rstride + s_q1 * 4));
                *(float4*)(dst + s_r0 * 256 + s_q0 * 4) = v0;
                *(float4*)(dst + s_r1 * 256 + s_q1 * 4) = v1;
            }

            // compute chunk c
            {
                const float* buf = h_c + (c & 1) * (16 * 256);
                const ull* wc = wp + c * 8;
                #pragma unroll
                for (int bi = 0; bi < 16; bi++) {
                    const ulonglong2* hp =
                        (const ulonglong2*)(buf + bi * 256 + w * 16);
                    ulonglong2 u0 = hp[0];
                    ulonglong2 u1 = hp[1];
                    ulonglong2 u2 = hp[2];
                    ulonglong2 u3 = hp[3];
                    ull a0 = ffma2(u0.x, wc[0], 0ull);
                    ull a1 = ffma2(u0.y, wc[1], 0ull);
                    a0 = ffma2(u1.x, wc[2], a0);
                    a1 = ffma2(u1.y, wc[3], a1);
                    a0 = ffma2(u2.x, wc[4], a0);
                    a1 = ffma2(u2.y, wc[5], a1);
                    a0 = ffma2(u3.x, wc[6], a0);
                    a1 = ffma2(u3.y, wc[7], a1);
                    a0 = fadd2(a0, a1);
                    acc[bi] += lo_f(a0) + hi_f(a0);
                }
            }

            if (c < 2 && t > 0 && tid == 0)
                while (ld_acq(&g_flag[FLAG_IDX(gb, c + 2)]) < target) { }
            if (c < 3) __syncthreads();
        }

        // ---- cross-warp reduce + epilogue ----
        #pragma unroll
        for (int bi = 0; bi < 16; bi++)
            red_s[(bi * 32 + l) * 17 + w] = acc[bi];
        __syncthreads();

        {
            const float* rp = red_s + (bi_e * 32 + col_e) * 17;
            float s = 0.0f;
            #pragma unroll
            for (int ww = 0; ww < 16; ww++) s += rp[ww];
            const float val = tanhf(xp_val + s + bh_r);
            hidden[oidx] = val;
            if (t == TSTEPS - 1)
                lasth[(size_t)b_e * HDIM + h_e] = val;
        }

        // ---- publish: bar establishes happens-before, then release-add ----
        __syncthreads();
        if (tid == 0) red_rel_add1(&g_flag[my_flag]);
    }
}

// ============================================================
// Launch
// ============================================================
extern "C" void kernel_launch(void* const* d_in, const int* in_sizes, int n_in,
                              void* d_out, int out_size) {
    const float* emb = (const float*)d_in[0];   // [B,T,I]
    const float* h0  = (const float*)d_in[1];   // [B,H]
    const float* Wx  = (const float*)d_in[2];   // [H,I]
    const float* bx  = (const float*)d_in[3];   // [H]
    const float* Wh  = (const float*)d_in[4];   // [H,H]
    const float* bh  = (const float*)d_in[5];   // [H]

    float* hidden = (float*)d_out;                            // [B,T,H]
    float* lasth  = hidden + (size_t)BDIM * TSTEPS * HDIM;    // [B,H]

    cudaFuncSetAttribute(rnn_scan, cudaFuncAttributeMaxDynamicSharedMemorySize,
                         SMEM_BYTES);

    // xp = emb @ Wx^T + bx (also resets scan flags)
    dim3 g1(HDIM / 128, (BDIM * TSTEPS) / 128);
    gemm_xproj<<<g1, 256>>>(emb, Wx, bx, hidden);

    // dataflow-synced persistent scan
    rnn_scan<<<NCTAS, NTHREADS, SMEM_BYTES>>>(hidden, h0, Wh, bh, lasth);
}

// round 6
// speedup vs baseline: 1.8678x; 1.1242x over previous
#include <cuda_runtime.h>
#include <cuda_bf16.h>
#include <math.h>

// Problem constants
#define BDIM 64
#define TSTEPS 512
#define IDIM 512
#define HDIM 1024

#define NCTAS 128
#define NTHREADS 512

typedef unsigned long long ull;

// ---------- packed f32x2 helpers ----------
__device__ __forceinline__ ull ffma2(ull a, ull b, ull c) {
    ull d;
    asm("fma.rn.f32x2 %0, %1, %2, %3;" : "=l"(d) : "l"(a), "l"(b), "l"(c));
    return d;
}
__device__ __forceinline__ float lo_f(ull v) {
    return __uint_as_float((unsigned)(v & 0xffffffffull));
}
__device__ __forceinline__ float hi_f(ull v) {
    return __uint_as_float((unsigned)(v >> 32));
}
__device__ __forceinline__ ull dup_f(float x) {
    unsigned u = __float_as_uint(x);
    return ((ull)u << 32) | u;
}
__device__ __forceinline__ unsigned ld_acq(const unsigned* p) {
    unsigned v;
    asm volatile("ld.acquire.gpu.global.u32 %0, [%1];" : "=r"(v) : "l"(p) : "memory");
    return v;
}
__device__ __forceinline__ void red_rel_add1(unsigned* p) {
    asm volatile("red.release.gpu.global.add.u32 [%0], 1;" :: "l"(p) : "memory");
}

// One flag per batch-group, each in its own 128B sector
__device__ unsigned g_flag[4 * 32];
#define FLAG_IDX(gb) ((gb) * 32)

// ============================================================
// Kernel 1: xp = embeddings @ Wx^T + bx  -> written into hidden
// NT gemm, BM=128 BN=128 BK=16, 256 threads, 8x8/thread, FFMA2.
// Also resets the scan flags (block (0,0)).
// ============================================================
__global__ __launch_bounds__(256) void gemm_xproj(
    const float* __restrict__ A,
    const float* __restrict__ Bw,
    const float* __restrict__ bx,
    float* __restrict__ C)
{
    if (blockIdx.x == 0 && blockIdx.y == 0 && threadIdx.x < 4)
        g_flag[threadIdx.x * 32] = 0u;

    const int K = IDIM;
    const int N = HDIM;
    __shared__ ull   As_d[16][130];   // duplicated-pack rows: (a,a)
    __shared__ float Bs[16][132];

    const int bm = blockIdx.y * 128;
    const int bn = blockIdx.x * 128;
    const int tid = threadIdx.x;
    const int tx = tid & 15;          // 8 cols
    const int ty = tid >> 4;          // 8 rows

    ull acc[8][4];
    #pragma unroll
    for (int i = 0; i < 8; i++)
        #pragma unroll
        for (int j = 0; j < 4; j++) acc[i][j] = 0ull;

    for (int kt = 0; kt < K; kt += 16) {
        #pragma unroll
        for (int i = 0; i < 2; i++) {
            int f = tid + 256 * i;
            int row = f >> 2, quad = f & 3;
            float4 v = *(const float4*)(A + (size_t)(bm + row) * K + kt + quad * 4);
            As_d[quad * 4 + 0][row] = dup_f(v.x);
            As_d[quad * 4 + 1][row] = dup_f(v.y);
            As_d[quad * 4 + 2][row] = dup_f(v.z);
            As_d[quad * 4 + 3][row] = dup_f(v.w);
        }
        #pragma unroll
        for (int i = 0; i < 2; i++) {
            int f = tid + 256 * i;
            int col = f >> 2, quad = f & 3;
            float4 v = *(const float4*)(Bw + (size_t)(bn + col) * K + kt + quad * 4);
            Bs[quad * 4 + 0][col] = v.x;
            Bs[quad * 4 + 1][col] = v.y;
            Bs[quad * 4 + 2][col] = v.z;
            Bs[quad * 4 + 3][col] = v.w;
        }
        __syncthreads();

        #pragma unroll
        for (int k = 0; k < 16; k++) {
            ulonglong2 a01 = *(const ulonglong2*)&As_d[k][ty * 8 + 0];
            ulonglong2 a23 = *(const ulonglong2*)&As_d[k][ty * 8 + 2];
            ulonglong2 a45 = *(const ulonglong2*)&As_d[k][ty * 8 + 4];
            ulonglong2 a67 = *(const ulonglong2*)&As_d[k][ty * 8 + 6];
            ulonglong2 b03 = *(const ulonglong2*)&Bs[k][tx * 8 + 0];
            ulonglong2 b47 = *(const ulonglong2*)&Bs[k][tx * 8 + 4];
            ull ad[8] = {a01.x, a01.y, a23.x, a23.y, a45.x, a45.y, a67.x, a67.y};
            ull bp[4] = {b03.x, b03.y, b47.x, b47.y};
            #pragma unroll
            for (int i = 0; i < 8; i++)
                #pragma unroll
                for (int j = 0; j < 4; j++)
                    acc[i][j] = ffma2(ad[i], bp[j], acc[i][j]);
        }
        __syncthreads();
    }

    float4 bx0 = *(const float4*)(bx + bn + tx * 8);
    float4 bx1 = *(const float4*)(bx + bn + tx * 8 + 4);
    #pragma unroll
    for (int i = 0; i < 8; i++) {
        float4 o0, o1;
        o0.x = lo_f(acc[i][0]) + bx0.x;
        o0.y = hi_f(acc[i][0]) + bx0.y;
        o0.z = lo_f(acc[i][1]) + bx0.z;
        o0.w = hi_f(acc[i][1]) + bx0.w;
        o1.x = lo_f(acc[i][2]) + bx1.x;
        o1.y = hi_f(acc[i][2]) + bx1.y;
        o1.z = lo_f(acc[i][3]) + bx1.z;
        o1.w = hi_f(acc[i][3]) + bx1.w;
        float* cp = C + (size_t)(bm + ty * 8 + i) * N + bn + tx * 8;
        *(float4*)(cp)     = o0;
        *(float4*)(cp + 4) = o1;
    }
}

// ============================================================
// Recurrent scan, col-paired tiling (nc=2).
// 128 CTAs x 512 threads. CTA = (gb: 16 batches) x (cg: 32 H cols).
// Thread t: cp = t&15 -> cols {cg*32+2cp, +1}; kq = t>>4 -> k in
// [32kq, 32kq+32). Each 16B h-load feeds 4 ffma2 (vs 2 before):
// 128 LDS.128/thread/step. h rows stored padded (36-float groups)
// so the two half-warp broadcast addresses hit distinct banks.
// Partial reduce: shfl_xor(16) combines the warp's two kq halves,
// then 16-warp smem reduce as before. One dataflow flag per gb.
// ============================================================
#define HROW 1152                        // 32 groups * 36 floats
#define HS_FLOATS  (16 * HROW)           // 73728 floats
#define RED_FLOATS (16 * 32 * 17)        // 8704 floats
#define SMEM_BYTES ((HS_FLOATS + RED_FLOATS) * 4)

__global__ __launch_bounds__(NTHREADS, 1) void rnn_scan(
    float* __restrict__ hidden,      // [B, T, H] holds xp, overwritten with h
    const float* __restrict__ h0,    // [B, H]
    const float* __restrict__ Wh,    // [H, H]
    const float* __restrict__ bh,    // [H]
    float* __restrict__ lasth)       // [B, H]
{
    extern __shared__ float smem[];
    float* h_s   = smem;               // [16][HROW]
    float* red_s = smem + HS_FLOATS;   // [bi][col][warp] pad 17

    const int tid = threadIdx.x;
    const int l = tid & 31;
    const int w = tid >> 5;            // warp 0..15
    const int cp = l & 15;             // col pair index
    const int kq = tid >> 4;           // 0..31, k range [32kq, 32kq+32)
    const int gb = blockIdx.x & 3;
    const int cg = blockIdx.x >> 2;
    const int b0 = gb * 16;
    const int c0 = cg * 32 + 2 * cp;   // first of this thread's 2 cols

    // Persistent packed weights: 2 cols x 32 k = 32 ull
    ull wp0[16], wp1[16];
    {
        const ulonglong2* s0 = (const ulonglong2*)(Wh + (size_t)c0 * HDIM + kq * 32);
        const ulonglong2* s1 = (const ulonglong2*)(Wh + (size_t)(c0 + 1) * HDIM + kq * 32);
        #pragma unroll
        for (int q = 0; q < 8; q++) {
            ulonglong2 v = s0[q];
            wp0[2 * q + 0] = v.x;
            wp0[2 * q + 1] = v.y;
            ulonglong2 u = s1[q];
            wp1[2 * q + 0] = u.x;
            wp1[2 * q + 1] = u.y;
        }
    }

    // Epilogue mapping
    const int bi_e = tid >> 5;
    const int col_e = tid & 31;
    const int b_e = b0 + bi_e;
    const int h_e = cg * 32 + col_e;
    const float bh_r = bh[h_e];

    // This thread's partial-store column (even half stores col 2cp, odd 2cp+1)
    const int colsel = 2 * cp + (l >> 4);

    const float* hk = h_s + kq * 36;   // k-offset within padded row

    float acc0[16], acc1[16];

    for (int t = 0; t < TSTEPS; t++) {
        // ---- wait for all 32 col-CTAs of this group to publish h_{t-1} ----
        if (t > 0 && tid == 0) {
            const unsigned target = 32u * (unsigned)t;
            while (ld_acq(&g_flag[FLAG_IDX(gb)]) < target) { }
        }
        __syncthreads();

        // ---- stage h_prev[16][1024] into padded smem rows ----
        {
            const float* base = (t == 0)
                ? (h0 + (size_t)b0 * HDIM)
                : (hidden + ((size_t)b0 * TSTEPS + (t - 1)) * HDIM);
            const size_t rstride = (t == 0) ? (size_t)HDIM : (size_t)TSTEPS * HDIM;
            #pragma unroll
            for (int i = 0; i < 8; i++) {
                int idx = tid + NTHREADS * i;       // 0..4095 float4 slots
                int r = idx >> 8;                   // batch row 0..15
                int g = idx & 255;                  // float4 slot in row
                float4 v = __ldcg((const float4*)(base + r * rstride + g * 4));
                *(float4*)(h_s + r * HROW + (g >> 3) * 36 + (g & 7) * 4) = v;
            }
        }

        // xp for this step (own slot; independent of h_prev)
        const size_t oidx = ((size_t)b_e * TSTEPS + t) * HDIM + h_e;
        const float xp_val = __ldg(hidden + oidx);

        __syncthreads();

        // ---- 16 batches x (2 cols x 32 k) ----
        #pragma unroll 4
        for (int bi = 0; bi < 16; bi++) {
            const ulonglong2* hp = (const ulonglong2*)(hk + bi * HROW);
            ull a0 = 0ull, a0b = 0ull, a1 = 0ull, a1b = 0ull;
            #pragma unroll
            for (int q = 0; q < 8; q++) {
                ulonglong2 u = hp[q];
                a0  = ffma2(u.x, wp0[2 * q + 0], a0);
                a1  = ffma2(u.x, wp1[2 * q + 0], a1);
                a0b = ffma2(u.y, wp0[2 * q + 1], a0b);
                a1b = ffma2(u.y, wp1[2 * q + 1], a1b);
            }
            acc0[bi] = (lo_f(a0) + hi_f(a0)) + (lo_f(a0b) + hi_f(a0b));
            acc1[bi] = (lo_f(a1) + hi_f(a1)) + (lo_f(a1b) + hi_f(a1b));
        }

        // ---- combine the warp's two kq halves, store partials ----
        #pragma unroll
        for (int bi = 0; bi < 16; bi++) {
            acc0[bi] += __shfl_xor_sync(0xffffffffu, acc0[bi], 16);
            acc1[bi] += __shfl_xor_sync(0xffffffffu, acc1[bi], 16);
            float v = (l < 16) ? acc0[bi] : acc1[bi];
            red_s[(bi * 32 + colsel) * 17 + w] = v;
        }
        __syncthreads();

        // ---- final 16-warp reduce + epilogue ----
        {
            const float* rp = red_s + (bi_e * 32 + col_e) * 17;
            float s = 0.0f;
            #pragma unroll
            for (int ww = 0; ww < 16; ww++) s += rp[ww];
            const float val = tanhf(xp_val + s + bh_r);
            hidden[oidx] = val;
            if (t == TSTEPS - 1)
                lasth[(size_t)b_e * HDIM + h_e] = val;
        }

        // ---- publish ----
        __syncthreads();
        if (tid == 0) red_rel_add1(&g_flag[FLAG_IDX(gb)]);
    }
}

// ============================================================
// Launch
// ============================================================
extern "C" void kernel_launch(void* const* d_in, const int* in_sizes, int n_in,
                              void* d_out, int out_size) {
    const float* emb = (const float*)d_in[0];   // [B,T,I]
    const float* h0  = (const float*)d_in[1];   // [B,H]
    const float* Wx  = (const float*)d_in[2];   // [H,I]
    const float* bx  = (const float*)d_in[3];   // [H]
    const float* Wh  = (const float*)d_in[4];   // [H,H]
    const float* bh  = (const float*)d_in[5];   // [H]

    float* hidden = (float*)d_out;                            // [B,T,H]
    float* lasth  = hidden + (size_t)BDIM * TSTEPS * HDIM;    // [B,H]

    cudaFuncSetAttribute(rnn_scan, cudaFuncAttributeMaxDynamicSharedMemorySize,
                         SMEM_BYTES);

    // xp = emb @ Wx^T + bx (also resets scan flags)
    dim3 g1(HDIM / 128, (BDIM * TSTEPS) / 128);
    gemm_xproj<<<g1, 256>>>(emb, Wx, bx, hidden);

    // dataflow-synced persistent scan
    rnn_scan<<<NCTAS, NTHREADS, SMEM_BYTES>>>(hidden, h0, Wh, bh, lasth);
}

// round 8
// speedup vs baseline: 2.0477x; 1.0963x over previous
#include <cuda_runtime.h>
#include <cuda_bf16.h>
#include <math.h>

// Problem constants
#define BDIM 64
#define TSTEPS 512
#define IDIM 512
#define HDIM 1024

#define NCTAS 128
#define NTHREADS 1024

typedef unsigned long long ull;

// ---------- packed f32x2 helpers ----------
__device__ __forceinline__ ull ffma2(ull a, ull b, ull c) {
    ull d;
    asm("fma.rn.f32x2 %0, %1, %2, %3;" : "=l"(d) : "l"(a), "l"(b), "l"(c));
    return d;
}
__device__ __forceinline__ ull fadd2(ull a, ull b) {
    ull d;
    asm("add.rn.f32x2 %0, %1, %2;" : "=l"(d) : "l"(a), "l"(b));
    return d;
}
__device__ __forceinline__ float lo_f(ull v) {
    return __uint_as_float((unsigned)(v & 0xffffffffull));
}
__device__ __forceinline__ float hi_f(ull v) {
    return __uint_as_float((unsigned)(v >> 32));
}
__device__ __forceinline__ ull dup_f(float x) {
    unsigned u = __float_as_uint(x);
    return ((ull)u << 32) | u;
}
__device__ __forceinline__ unsigned ld_acq(const unsigned* p) {
    unsigned v;
    asm volatile("ld.acquire.gpu.global.u32 %0, [%1];" : "=r"(v) : "l"(p) : "memory");
    return v;
}
__device__ __forceinline__ void red_rel_add1(unsigned* p) {
    asm volatile("red.release.gpu.global.add.u32 [%0], 1;" :: "l"(p) : "memory");
}

// One flag per batch-group, each in its own 128B sector
__device__ unsigned g_flag[4 * 32];
#define FLAG_IDX(gb) ((gb) * 32)

// ============================================================
// Kernel 1: xp = embeddings @ Wx^T + bx  -> written into hidden
// NT gemm, BM=128 BN=128 BK=16, 256 threads, 8x8/thread, FFMA2.
// Also resets the scan flags (block (0,0)).
// ============================================================
__global__ __launch_bounds__(256) void gemm_xproj(
    const float* __restrict__ A,
    const float* __restrict__ Bw,
    const float* __restrict__ bx,
    float* __restrict__ C)
{
    if (blockIdx.x == 0 && blockIdx.y == 0 && threadIdx.x < 4)
        g_flag[threadIdx.x * 32] = 0u;

    const int K = IDIM;
    const int N = HDIM;
    __shared__ ull   As_d[16][130];   // duplicated-pack rows: (a,a)
    __shared__ float Bs[16][132];

    const int bm = blockIdx.y * 128;
    const int bn = blockIdx.x * 128;
    const int tid = threadIdx.x;
    const int tx = tid & 15;          // 8 cols
    const int ty = tid >> 4;          // 8 rows

    ull acc[8][4];
    #pragma unroll
    for (int i = 0; i < 8; i++)
        #pragma unroll
        for (int j = 0; j < 4; j++) acc[i][j] = 0ull;

    for (int kt = 0; kt < K; kt += 16) {
        #pragma unroll
        for (int i = 0; i < 2; i++) {
            int f = tid + 256 * i;
            int row = f >> 2, quad = f & 3;
            float4 v = *(const float4*)(A + (size_t)(bm + row) * K + kt + quad * 4);
            As_d[quad * 4 + 0][row] = dup_f(v.x);
            As_d[quad * 4 + 1][row] = dup_f(v.y);
            As_d[quad * 4 + 2][row] = dup_f(v.z);
            As_d[quad * 4 + 3][row] = dup_f(v.w);
        }
        #pragma unroll
        for (int i = 0; i < 2; i++) {
            int f = tid + 256 * i;
            int col = f >> 2, quad = f & 3;
            float4 v = *(const float4*)(Bw + (size_t)(bn + col) * K + kt + quad * 4);
            Bs[quad * 4 + 0][col] = v.x;
            Bs[quad * 4 + 1][col] = v.y;
            Bs[quad * 4 + 2][col] = v.z;
            Bs[quad * 4 + 3][col] = v.w;
        }
        __syncthreads();

        #pragma unroll
        for (int k = 0; k < 16; k++) {
            ulonglong2 a01 = *(const ulonglong2*)&As_d[k][ty * 8 + 0];
            ulonglong2 a23 = *(const ulonglong2*)&As_d[k][ty * 8 + 2];
            ulonglong2 a45 = *(const ulonglong2*)&As_d[k][ty * 8 + 4];
            ulonglong2 a67 = *(const ulonglong2*)&As_d[k][ty * 8 + 6];
            ulonglong2 b03 = *(const ulonglong2*)&Bs[k][tx * 8 + 0];
            ulonglong2 b47 = *(const ulonglong2*)&Bs[k][tx * 8 + 4];
            ull ad[8] = {a01.x, a01.y, a23.x, a23.y, a45.x, a45.y, a67.x, a67.y};
            ull bp[4] = {b03.x, b03.y, b47.x, b47.y};
            #pragma unroll
            for (int i = 0; i < 8; i++)
                #pragma unroll
                for (int j = 0; j < 4; j++)
                    acc[i][j] = ffma2(ad[i], bp[j], acc[i][j]);
        }
        __syncthreads();
    }

    float4 bx0 = *(const float4*)(bx + bn + tx * 8);
    float4 bx1 = *(const float4*)(bx + bn + tx * 8 + 4);
    #pragma unroll
    for (int i = 0; i < 8; i++) {
        float4 o0, o1;
        o0.x = lo_f(acc[i][0]) + bx0.x;
        o0.y = hi_f(acc[i][0]) + bx0.y;
        o0.z = lo_f(acc[i][1]) + bx0.z;
        o0.w = hi_f(acc[i][1]) + bx0.w;
        o1.x = lo_f(acc[i][2]) + bx1.x;
        o1.y = hi_f(acc[i][2]) + bx1.y;
        o1.z = lo_f(acc[i][3]) + bx1.z;
        o1.w = hi_f(acc[i][3]) + bx1.w;
        float* cp = C + (size_t)(bm + ty * 8 + i) * N + bn + tx * 8;
        *(float4*)(cp)     = o0;
        *(float4*)(cp + 4) = o1;
    }
}

// ============================================================
// Recurrent scan, high-occupancy (1024 threads, 8 warps/SMSP).
// 128 CTAs. CTA = (gb: 16 batches) x (cg: 32 H cols).
// Thread (w, l): cols {cg*32 + 2*(l&15), +1}; k in [kq*16, kq*16+16)
// where kq = 2w + (l>>4)  (64 k-groups x 16 col-pairs = 1024 threads).
// Weights: 2 cols x 16 k = 16 ull = 32 regs -> fits 64-reg budget.
// Per bi: 4 LDS.128 (half-warp broadcast), 16 ffma2, immediate
// shfl_xor(16) + smem partial store (no accumulator arrays).
// Final: 32-warp smem reduce (threads 0..511), tanh, in-place store.
// h rows: 64 groups of 16 floats padded to 20 (80 B = 16B-aligned for
// every kq, and the two half-warp broadcast addresses land in
// different banks).
// ============================================================
#define HROW 1280                        // 64 groups * 20 floats
#define HS_FLOATS  (16 * HROW)           // 20480 floats
#define RED_FLOATS (16 * 32 * 33)        // 16896 floats
#define SMEM_BYTES ((HS_FLOATS + RED_FLOATS) * 4)

__global__ __launch_bounds__(NTHREADS, 1) void rnn_scan(
    float* __restrict__ hidden,      // [B, T, H] holds xp, overwritten with h
    const float* __restrict__ h0,    // [B, H]
    const float* __restrict__ Wh,    // [H, H]
    const float* __restrict__ bh,    // [H]
    float* __restrict__ lasth)       // [B, H]
{
    extern __shared__ float smem[];
    float* h_s   = smem;               // [16][HROW]
    float* red_s = smem + HS_FLOATS;   // [bi][col][warp] pad 33

    const int tid = threadIdx.x;
    const int l = tid & 31;
    const int w = tid >> 5;            // warp 0..31
    const int cp = l & 15;             // col-pair index
    const int kh = l >> 4;             // 0/1: which kq of this warp
    const int kq = 2 * w + kh;         // 0..63
    const int gb = blockIdx.x & 3;
    const int cg = blockIdx.x >> 2;
    const int b0 = gb * 16;
    const int c0 = cg * 32 + 2 * cp;   // first of this thread's 2 cols

    // Persistent packed weights: 2 cols x 8 k-pairs = 16 ull (32 regs)
    ull wp0[8], wp1[8];
    {
        const ulonglong2* s0 = (const ulonglong2*)(Wh + (size_t)c0 * HDIM + kq * 16);
        const ulonglong2* s1 = (const ulonglong2*)(Wh + (size_t)(c0 + 1) * HDIM + kq * 16);
        #pragma unroll
        for (int q = 0; q < 4; q++) {
            ulonglong2 v = s0[q];
            wp0[2 * q + 0] = v.x;
            wp0[2 * q + 1] = v.y;
            ulonglong2 u = s1[q];
            wp1[2 * q + 0] = u.x;
            wp1[2 * q + 1] = u.y;
        }
    }

    // Partial-store column: lanes 0-15 store even col of their pair, 16-31 odd
    const int colsel = 2 * cp + kh;

    // Epilogue mapping (threads 0..511 only)
    const int bi_e = (tid >> 5) & 15;
    const int col_e = tid & 31;
    const int b_e = b0 + bi_e;
    const int h_e = cg * 32 + col_e;
    const float bh_r = bh[h_e];

    const float* hk = h_s + kq * 20;   // 80B-aligned k window in a padded row

    for (int t = 0; t < TSTEPS; t++) {
        // ---- wait for all 32 col-CTAs of this group to publish h_{t-1} ----
        if (t > 0 && tid == 0) {
            const unsigned target = 32u * (unsigned)t;
            while (ld_acq(&g_flag[FLAG_IDX(gb)]) < target) { }
        }
        __syncthreads();

        // ---- stage h_prev[16][1024] into padded smem rows ----
        {
            const float* base = (t == 0)
                ? (h0 + (size_t)b0 * HDIM)
                : (hidden + ((size_t)b0 * TSTEPS + (t - 1)) * HDIM);
            const size_t rstride = (t == 0) ? (size_t)HDIM : (size_t)TSTEPS * HDIM;
            #pragma unroll
            for (int i = 0; i < 4; i++) {
                int idx = tid + NTHREADS * i;       // 0..4095 float4 slots
                int r = idx >> 8;                   // batch row 0..15
                int g = idx & 255;                  // float4 slot in row
                float4 v = __ldcg((const float4*)(base + r * rstride + g * 4));
                *(float4*)(h_s + r * HROW + (g >> 2) * 20 + (g & 3) * 4) = v;
            }
        }

        // xp for this step (own slot; independent of h_prev)
        size_t oidx = 0;
        float xp_val = 0.0f;
        if (tid < 512) {
            oidx = ((size_t)b_e * TSTEPS + t) * HDIM + h_e;
            xp_val = __ldg(hidden + oidx);
        }

        __syncthreads();

        // ---- 16 batches x (2 cols x 16 k); reduce-and-store per bi ----
        #pragma unroll 4
        for (int bi = 0; bi < 16; bi++) {
            const ulonglong2* hp = (const ulonglong2*)(hk + bi * HROW);
            ulonglong2 u0 = hp[0];
            ulonglong2 u1 = hp[1];
            ull a0  = ffma2(u0.x, wp0[0], 0ull);
            ull a1  = ffma2(u0.x, wp1[0], 0ull);
            ull a0b = ffma2(u0.y, wp0[1], 0ull);
            ull a1b = ffma2(u0.y, wp1[1], 0ull);
            a0  = ffma2(u1.x, wp0[2], a0);
            a1  = ffma2(u1.x, wp1[2], a1);
            a0b = ffma2(u1.y, wp0[3], a0b);
            a1b = ffma2(u1.y, wp1[3], a1b);
            ulonglong2 u2 = hp[2];
            ulonglong2 u3 = hp[3];
            a0  = ffma2(u2.x, wp0[4], a0);
            a1  = ffma2(u2.x, wp1[4], a1);
            a0b = ffma2(u2.y, wp0[5], a0b);
            a1b = ffma2(u2.y, wp1[5], a1b);
            a0  = ffma2(u3.x, wp0[6], a0);
            a1  = ffma2(u3.x, wp1[6], a1);
            a0b = ffma2(u3.y, wp0[7], a0b);
            a1b = ffma2(u3.y, wp1[7], a1b);
            a0 = fadd2(a0, a0b);
            a1 = fadd2(a1, a1b);
            float s0 = lo_f(a0) + hi_f(a0);
            float s1 = lo_f(a1) + hi_f(a1);
            // combine the warp's two kq halves
            s0 += __shfl_xor_sync(0xffffffffu, s0, 16);
            s1 += __shfl_xor_sync(0xffffffffu, s1, 16);
            red_s[(bi * 32 + colsel) * 33 + w] = (l < 16) ? s0 : s1;
        }
        __syncthreads();

        // ---- final 32-warp reduce + epilogue (threads 0..511) ----
        if (tid < 512) {
            const float* rp = red_s + (bi_e * 32 + col_e) * 33;
            float s = 0.0f;
            #pragma unroll
            for (int ww = 0; ww < 32; ww++) s += rp[ww];
            const float val = tanhf(xp_val + s + bh_r);
            hidden[oidx] = val;
            if (t == TSTEPS - 1)
                lasth[(size_t)b_e * HDIM + h_e] = val;
        }

        // ---- publish ----
        __syncthreads();
        if (tid == 0) red_rel_add1(&g_flag[FLAG_IDX(gb)]);
    }
}

// ============================================================
// Launch
// ============================================================
extern "C" void kernel_launch(void* const* d_in, const int* in_sizes, int n_in,
                              void* d_out, int out_size) {
    const float* emb = (const float*)d_in[0];   // [B,T,I]
    const float* h0  = (const float*)d_in[1];   // [B,H]
    const float* Wx  = (const float*)d_in[2];   // [H,I]
    const float* bx  = (const float*)d_in[3];   // [H]
    const float* Wh  = (const float*)d_in[4];   // [H,H]
    const float* bh  = (const float*)d_in[5];   // [H]

    float* hidden = (float*)d_out;                            // [B,T,H]
    float* lasth  = hidden + (size_t)BDIM * TSTEPS * HDIM;    // [B,H]

    cudaFuncSetAttribute(rnn_scan, cudaFuncAttributeMaxDynamicSharedMemorySize,
                         SMEM_BYTES);

    // xp = emb @ Wx^T + bx (also resets scan flags)
    dim3 g1(HDIM / 128, (BDIM * TSTEPS) / 128);
    gemm_xproj<<<g1, 256>>>(emb, Wx, bx, hidden);

    // dataflow-synced persistent scan
    rnn_scan<<<NCTAS, NTHREADS, SMEM_BYTES>>>(hidden, h0, Wh, bh, lasth);
}